// round 1
// baseline (speedup 1.0000x reference)
#include <cuda_runtime.h>
#include <math.h>

#define DHID 128
#define MAX_ENTS 100000
#define MAX_RELS 1000

// Scratch (allocation-free rule: __device__ globals)
__device__ float g_hW[MAX_ENTS * DHID];     // (normalized h) @ W_neighbor
__device__ float g_relW[MAX_RELS * DHID];   // rel_emb @ W_neighbor

// ---------------------------------------------------------------------------
// Kernel A: L2-normalize 64 rows of ent_emb, then compute h@Wn -> g_hW and
// h@Ws -> agg (d_out, which doubles as the scatter accumulator).
// Block: 256 threads, 64 rows, output tile 64x256 (two 128-wide matrices).
// Shared: Wc[128][256] (Wn|Ws interleaved by column) + hs[64][128].
// ---------------------------------------------------------------------------
extern "C" __global__ void __launch_bounds__(256)
k_norm_dual_gemm(const float* __restrict__ ent,
                 const float* __restrict__ Wn,
                 const float* __restrict__ Ws,
                 float* __restrict__ hW,
                 float* __restrict__ agg,
                 int N)
{
    extern __shared__ float sm[];
    float* Wc = sm;                 // 128*256
    float* hs = sm + 128 * 256;     // 64*128
    const int tid  = threadIdx.x;
    const int base = blockIdx.x * 64;

    // Load combined weight tile [k][c], c<128 -> Wn, else Ws
    for (int t = tid; t < (128 * 256) / 4; t += 256) {
        int word = t * 4;
        int k = word >> 8;
        int c = word & 255;
        float4 v;
        if (c < 128) v = *(const float4*)(Wn + k * 128 + c);
        else         v = *(const float4*)(Ws + k * 128 + (c - 128));
        *(float4*)(Wc + word) = v;
    }

    // Normalize 64 rows into hs (warp w handles rows 8w..8w+7)
    const int lane = tid & 31;
    const int w    = tid >> 5;
    for (int rr = 0; rr < 8; rr++) {
        int row  = w * 8 + rr;
        int node = base + row;
        float4 v = make_float4(0.f, 0.f, 0.f, 0.f);
        if (node < N) v = *(const float4*)(ent + (size_t)node * 128 + lane * 4);
        float ss = v.x * v.x + v.y * v.y + v.z * v.z + v.w * v.w;
        #pragma unroll
        for (int off = 16; off > 0; off >>= 1)
            ss += __shfl_xor_sync(0xffffffffu, ss, off);
        float n  = sqrtf(ss);
        float rn = 1.0f / fmaxf(n, 1e-12f);
        float4 o = make_float4(v.x * rn, v.y * rn, v.z * rn, v.w * rn);
        *(float4*)(hs + row * 128 + lane * 4) = o;
    }
    __syncthreads();

    // Register-tiled GEMM: thread = (ty rowgroup of 8, tx) covering cols tx+32*i
    const int tx = tid & 31;
    const int ty = tid >> 5;
    const int r0 = ty * 8;
    float acc[8][8];
    #pragma unroll
    for (int j = 0; j < 8; j++)
        #pragma unroll
        for (int i = 0; i < 8; i++) acc[j][i] = 0.f;

    #pragma unroll 4
    for (int k = 0; k < 128; k++) {
        float a[8], b[8];
        #pragma unroll
        for (int j = 0; j < 8; j++) a[j] = hs[(r0 + j) * 128 + k];   // broadcast
        #pragma unroll
        for (int i = 0; i < 8; i++) b[i] = Wc[k * 256 + tx + 32 * i]; // conflict-free
        #pragma unroll
        for (int j = 0; j < 8; j++)
            #pragma unroll
            for (int i = 0; i < 8; i++) acc[j][i] += a[j] * b[i];
    }

    #pragma unroll
    for (int j = 0; j < 8; j++) {
        int node = base + r0 + j;
        if (node >= N) continue;
        #pragma unroll
        for (int i = 0; i < 8; i++) {
            int c = tx + 32 * i;
            if (c < 128) hW[(size_t)node * 128 + c]          = acc[j][i];
            else         agg[(size_t)node * 128 + (c - 128)] = acc[j][i];
        }
    }
}

// ---------------------------------------------------------------------------
// Kernel B: relW = rel_emb @ W_neighbor   (1000x128 @ 128x128, tiny)
// ---------------------------------------------------------------------------
extern "C" __global__ void __launch_bounds__(256)
k_rel_gemm(const float* __restrict__ rel,
           const float* __restrict__ Wn,
           float* __restrict__ relW,
           int R)
{
    extern __shared__ float sm[];
    float* Wsh = sm;             // 128*128
    float* hs  = sm + 128 * 128; // 64*128
    const int tid  = threadIdx.x;
    const int base = blockIdx.x * 64;

    for (int t = tid; t < (128 * 128) / 4; t += 256)
        *(float4*)(Wsh + t * 4) = *(const float4*)(Wn + t * 4);

    const int lane = tid & 31;
    const int w    = tid >> 5;
    for (int rr = 0; rr < 8; rr++) {
        int row = w * 8 + rr;
        int r   = base + row;
        float4 v = make_float4(0.f, 0.f, 0.f, 0.f);
        if (r < R) v = *(const float4*)(rel + (size_t)r * 128 + lane * 4);
        *(float4*)(hs + row * 128 + lane * 4) = v;
    }
    __syncthreads();

    const int tx = tid & 31;
    const int ty = tid >> 5;
    const int r0 = ty * 8;
    float acc[8][4];
    #pragma unroll
    for (int j = 0; j < 8; j++)
        #pragma unroll
        for (int i = 0; i < 4; i++) acc[j][i] = 0.f;

    #pragma unroll 4
    for (int k = 0; k < 128; k++) {
        float a[8], b[4];
        #pragma unroll
        for (int j = 0; j < 8; j++) a[j] = hs[(r0 + j) * 128 + k];
        #pragma unroll
        for (int i = 0; i < 4; i++) b[i] = Wsh[k * 128 + tx + 32 * i];
        #pragma unroll
        for (int j = 0; j < 8; j++)
            #pragma unroll
            for (int i = 0; i < 4; i++) acc[j][i] += a[j] * b[i];
    }

    #pragma unroll
    for (int j = 0; j < 8; j++) {
        int r = base + r0 + j;
        if (r >= R) continue;
        #pragma unroll
        for (int i = 0; i < 4; i++)
            relW[(size_t)r * 128 + tx + 32 * i] = acc[j][i];
    }
}

// ---------------------------------------------------------------------------
// Kernel C: edge scatter. One warp per edge; lane handles 4 columns.
// msg = (hW[src] + relW[etype]) * edge_norm; agg[dst] += msg (red.v4).
// hW (51.2 MB) and agg (51.2 MB) both fit in the 126 MB L2.
// ---------------------------------------------------------------------------
extern "C" __global__ void __launch_bounds__(256)
k_edge(const float* __restrict__ hW,
       const float* __restrict__ relW,
       const float* __restrict__ enorm,
       const int* __restrict__ src,
       const int* __restrict__ dst,
       const int* __restrict__ et,
       float* __restrict__ agg,
       int E)
{
    int e = blockIdx.x * 8 + (threadIdx.x >> 5);
    if (e >= E) return;
    int lane = threadIdx.x & 31;

    int   s = __ldg(src + e);
    int   d = __ldg(dst + e);
    int   t = __ldg(et + e);
    float n = __ldg(enorm + e);

    int c = lane * 4;
    float4 a = *(const float4*)(hW   + (size_t)s * 128 + c);
    float4 b = *(const float4*)(relW + (size_t)t * 128 + c);
    float4 v = make_float4((a.x + b.x) * n, (a.y + b.y) * n,
                           (a.z + b.z) * n, (a.w + b.w) * n);
    float* p = agg + (size_t)d * 128 + c;
    asm volatile("red.global.add.v4.f32 [%0], {%1,%2,%3,%4};"
                 :: "l"(p), "f"(v.x), "f"(v.y), "f"(v.z), "f"(v.w)
                 : "memory");
}

// ---------------------------------------------------------------------------
// Kernel D: h_cur = rrelu(agg); gate = sigmoid(h_cur @ Wt + b);
// out = gate*h_cur + (1-gate)*his.   In-place on d_out.
// ---------------------------------------------------------------------------
#define RRELU_SLOPE 0.22916666666666666f

extern "C" __global__ void __launch_bounds__(256)
k_final(float* __restrict__ x,          // d_out: agg in, result out
        const float* __restrict__ Wt,
        const float* __restrict__ bias,
        const float* __restrict__ his,
        int N)
{
    extern __shared__ float sm[];
    float* Wsh = sm;             // 128*128
    float* hs  = sm + 128 * 128; // 64*128 (post-rrelu h_cur)
    const int tid  = threadIdx.x;
    const int base = blockIdx.x * 64;

    for (int t = tid; t < (128 * 128) / 4; t += 256)
        *(float4*)(Wsh + t * 4) = *(const float4*)(Wt + t * 4);

    const int lane = tid & 31;
    const int w    = tid >> 5;
    for (int rr = 0; rr < 8; rr++) {
        int row  = w * 8 + rr;
        int node = base + row;
        float4 v = make_float4(0.f, 0.f, 0.f, 0.f);
        if (node < N) v = *(const float4*)(x + (size_t)node * 128 + lane * 4);
        v.x = v.x >= 0.f ? v.x : RRELU_SLOPE * v.x;
        v.y = v.y >= 0.f ? v.y : RRELU_SLOPE * v.y;
        v.z = v.z >= 0.f ? v.z : RRELU_SLOPE * v.z;
        v.w = v.w >= 0.f ? v.w : RRELU_SLOPE * v.w;
        *(float4*)(hs + row * 128 + lane * 4) = v;
    }
    __syncthreads();

    const int tx = tid & 31;
    const int ty = tid >> 5;
    const int r0 = ty * 8;
    float acc[8][4];
    #pragma unroll
    for (int j = 0; j < 8; j++)
        #pragma unroll
        for (int i = 0; i < 4; i++) acc[j][i] = 0.f;

    #pragma unroll 4
    for (int k = 0; k < 128; k++) {
        float a[8], b[4];
        #pragma unroll
        for (int j = 0; j < 8; j++) a[j] = hs[(r0 + j) * 128 + k];
        #pragma unroll
        for (int i = 0; i < 4; i++) b[i] = Wsh[k * 128 + tx + 32 * i];
        #pragma unroll
        for (int j = 0; j < 8; j++)
            #pragma unroll
            for (int i = 0; i < 4; i++) acc[j][i] += a[j] * b[i];
    }

    #pragma unroll
    for (int j = 0; j < 8; j++) {
        int node = base + r0 + j;
        if (node >= N) continue;
        #pragma unroll
        for (int i = 0; i < 4; i++) {
            int c = tx + 32 * i;
            float tg = acc[j][i] + __ldg(bias + c);
            float g  = 1.0f / (1.0f + __expf(-tg));
            float hv = hs[(r0 + j) * 128 + c];
            float hh = __ldg(his + (size_t)node * 128 + c);
            x[(size_t)node * 128 + c] = g * hv + (1.0f - g) * hh;
        }
    }
}

// ---------------------------------------------------------------------------
extern "C" void kernel_launch(void* const* d_in, const int* in_sizes, int n_in,
                              void* d_out, int out_size)
{
    const float* ent   = (const float*)d_in[0];
    const float* rel   = (const float*)d_in[1];
    const float* his   = (const float*)d_in[2];
    const float* Wn    = (const float*)d_in[3];
    const float* Ws    = (const float*)d_in[4];
    const float* Wt    = (const float*)d_in[5];
    const float* bias  = (const float*)d_in[6];
    const float* enorm = (const float*)d_in[7];
    const int*   src   = (const int*)d_in[8];
    const int*   dst   = (const int*)d_in[9];
    const int*   et    = (const int*)d_in[10];

    int N = in_sizes[0] / DHID;
    int R = in_sizes[1] / DHID;
    int E = in_sizes[7];
    float* out = (float*)d_out;

    float *hW, *relW;
    cudaGetSymbolAddress((void**)&hW, g_hW);
    cudaGetSymbolAddress((void**)&relW, g_relW);

    const int smA = (128 * 256 + 64 * 128) * sizeof(float); // 160 KB
    const int smB = (128 * 128 + 64 * 128) * sizeof(float); //  96 KB
    cudaFuncSetAttribute(k_norm_dual_gemm, cudaFuncAttributeMaxDynamicSharedMemorySize, smA);
    cudaFuncSetAttribute(k_rel_gemm,       cudaFuncAttributeMaxDynamicSharedMemorySize, smB);
    cudaFuncSetAttribute(k_final,          cudaFuncAttributeMaxDynamicSharedMemorySize, smB);

    k_norm_dual_gemm<<<(N + 63) / 64, 256, smA>>>(ent, Wn, Ws, hW, out, N);
    k_rel_gemm<<<(R + 63) / 64, 256, smB>>>(rel, Wn, relW, R);
    k_edge<<<(E + 7) / 8, 256>>>(hW, relW, enorm, src, dst, et, out, E);
    k_final<<<(N + 63) / 64, 256, smB>>>(out, Wt, bias, his, N);
}

// round 2
// speedup vs baseline: 1.2615x; 1.2615x over previous
#include <cuda_runtime.h>
#include <math.h>

#define DHID 128
#define MAX_ENTS 100000
#define MAX_RELS 1000
#define RRELU_SLOPE 0.22916666666666666f

__device__ float g_hW[MAX_ENTS * DHID];
__device__ float g_relW[MAX_RELS * DHID];

typedef unsigned long long ull;

__device__ __forceinline__ ull pack2(float x, float y) {
    ull r; asm("mov.b64 %0, {%1, %2};" : "=l"(r) : "f"(x), "f"(y)); return r;
}
__device__ __forceinline__ void unpack2(ull v, float& x, float& y) {
    asm("mov.b64 {%0, %1}, %2;" : "=f"(x), "=f"(y) : "l"(v));
}
__device__ __forceinline__ void ffma2(ull& d, ull a, ull b) {
    asm("fma.rn.f32x2 %0, %1, %2, %3;" : "=l"(d) : "l"(a), "l"(b), "l"(d));
}

// ---------------------------------------------------------------------------
// Kernel A: normalize 64 rows; dual GEMM h@Wn -> hW, h@Ws -> agg(d_out).
// 512 threads, 16 warps x 4 rows, 4 cols/thread in each output (2 f32x2 pairs each).
// smem: Wc[128][256] (160KB total with hs[64][128]).
// ---------------------------------------------------------------------------
extern "C" __global__ void __launch_bounds__(512)
k_norm_dual_gemm(const float* __restrict__ ent,
                 const float* __restrict__ Wn,
                 const float* __restrict__ Ws,
                 float* __restrict__ hW,
                 float* __restrict__ agg,
                 int N)
{
    extern __shared__ float sm[];
    float* Wc = sm;                 // 128*256
    float* hs = sm + 128 * 256;     // 64*128
    const int tid  = threadIdx.x;
    const int base = blockIdx.x * 64;
    const int lane = tid & 31;
    const int w    = tid >> 5;      // 0..15

    // Load combined weight tile [k][c]: c<128 -> Wn, else Ws
    for (int t = tid; t < (128 * 256) / 4; t += 512) {
        int word = t * 4;
        int k = word >> 8;
        int c = word & 255;
        float4 v;
        if (c < 128) v = *(const float4*)(Wn + k * 128 + c);
        else         v = *(const float4*)(Ws + k * 128 + (c - 128));
        *(float4*)(Wc + word) = v;
    }

    // Normalize: warp w handles rows 4w..4w+3
    #pragma unroll
    for (int rr = 0; rr < 4; rr++) {
        int row  = w * 4 + rr;
        int node = base + row;
        float4 v = make_float4(0.f, 0.f, 0.f, 0.f);
        if (node < N) v = *(const float4*)(ent + (size_t)node * 128 + lane * 4);
        float ss = v.x * v.x + v.y * v.y + v.z * v.z + v.w * v.w;
        #pragma unroll
        for (int off = 16; off > 0; off >>= 1)
            ss += __shfl_xor_sync(0xffffffffu, ss, off);
        float rn = 1.0f / fmaxf(sqrtf(ss), 1e-12f);
        *(float4*)(hs + row * 128 + lane * 4) =
            make_float4(v.x * rn, v.y * rn, v.z * rn, v.w * rn);
    }
    __syncthreads();

    const int r0 = w * 4;
    ull accN[4][2], accS[4][2];
    #pragma unroll
    for (int j = 0; j < 4; j++) {
        accN[j][0] = accN[j][1] = pack2(0.f, 0.f);
        accS[j][0] = accS[j][1] = pack2(0.f, 0.f);
    }

    #pragma unroll 2
    for (int kk = 0; kk < 128; kk += 4) {
        float a[4][4];
        #pragma unroll
        for (int j = 0; j < 4; j++) {
            float4 v = *(const float4*)(hs + (r0 + j) * 128 + kk);
            a[j][0] = v.x; a[j][1] = v.y; a[j][2] = v.z; a[j][3] = v.w;
        }
        #pragma unroll
        for (int t = 0; t < 4; t++) {
            float4 bn = *(const float4*)(Wc + (kk + t) * 256 + lane * 4);
            float4 bs = *(const float4*)(Wc + (kk + t) * 256 + 128 + lane * 4);
            ull bn0 = pack2(bn.x, bn.y), bn1 = pack2(bn.z, bn.w);
            ull bs0 = pack2(bs.x, bs.y), bs1 = pack2(bs.z, bs.w);
            #pragma unroll
            for (int j = 0; j < 4; j++) {
                ull ap = pack2(a[j][t], a[j][t]);
                ffma2(accN[j][0], ap, bn0);
                ffma2(accN[j][1], ap, bn1);
                ffma2(accS[j][0], ap, bs0);
                ffma2(accS[j][1], ap, bs1);
            }
        }
    }

    #pragma unroll
    for (int j = 0; j < 4; j++) {
        int node = base + r0 + j;
        if (node >= N) continue;
        float4 on, os;
        unpack2(accN[j][0], on.x, on.y); unpack2(accN[j][1], on.z, on.w);
        unpack2(accS[j][0], os.x, os.y); unpack2(accS[j][1], os.z, os.w);
        *(float4*)(hW  + (size_t)node * 128 + lane * 4) = on;
        *(float4*)(agg + (size_t)node * 128 + lane * 4) = os;
    }
}

// ---------------------------------------------------------------------------
// Kernel B: relW = rel_emb @ W_neighbor (tiny: 1000x128)
// ---------------------------------------------------------------------------
extern "C" __global__ void __launch_bounds__(512)
k_rel_gemm(const float* __restrict__ rel,
           const float* __restrict__ Wn,
           float* __restrict__ relW,
           int R)
{
    extern __shared__ float sm[];
    float* Wsh = sm;             // 128*128
    float* hs  = sm + 128 * 128; // 64*128
    const int tid  = threadIdx.x;
    const int base = blockIdx.x * 64;
    const int lane = tid & 31;
    const int w    = tid >> 5;

    for (int t = tid; t < (128 * 128) / 4; t += 512)
        *(float4*)(Wsh + t * 4) = *(const float4*)(Wn + t * 4);

    #pragma unroll
    for (int rr = 0; rr < 4; rr++) {
        int row = w * 4 + rr;
        int r   = base + row;
        float4 v = make_float4(0.f, 0.f, 0.f, 0.f);
        if (r < R) v = *(const float4*)(rel + (size_t)r * 128 + lane * 4);
        *(float4*)(hs + row * 128 + lane * 4) = v;
    }
    __syncthreads();

    const int r0 = w * 4;
    ull acc[4][2];
    #pragma unroll
    for (int j = 0; j < 4; j++) acc[j][0] = acc[j][1] = pack2(0.f, 0.f);

    #pragma unroll 2
    for (int kk = 0; kk < 128; kk += 4) {
        float a[4][4];
        #pragma unroll
        for (int j = 0; j < 4; j++) {
            float4 v = *(const float4*)(hs + (r0 + j) * 128 + kk);
            a[j][0] = v.x; a[j][1] = v.y; a[j][2] = v.z; a[j][3] = v.w;
        }
        #pragma unroll
        for (int t = 0; t < 4; t++) {
            float4 b = *(const float4*)(Wsh + (kk + t) * 128 + lane * 4);
            ull b0 = pack2(b.x, b.y), b1 = pack2(b.z, b.w);
            #pragma unroll
            for (int j = 0; j < 4; j++) {
                ull ap = pack2(a[j][t], a[j][t]);
                ffma2(acc[j][0], ap, b0);
                ffma2(acc[j][1], ap, b1);
            }
        }
    }

    #pragma unroll
    for (int j = 0; j < 4; j++) {
        int r = base + r0 + j;
        if (r >= R) continue;
        float4 o;
        unpack2(acc[j][0], o.x, o.y); unpack2(acc[j][1], o.z, o.w);
        *(float4*)(relW + (size_t)r * 128 + lane * 4) = o;
    }
}

// ---------------------------------------------------------------------------
// Kernel C: edge scatter (L2-bound; hW + agg resident in 126MB L2)
// ---------------------------------------------------------------------------
extern "C" __global__ void __launch_bounds__(256)
k_edge(const float* __restrict__ hW,
       const float* __restrict__ relW,
       const float* __restrict__ enorm,
       const int* __restrict__ src,
       const int* __restrict__ dst,
       const int* __restrict__ et,
       float* __restrict__ agg,
       int E)
{
    int e = blockIdx.x * 8 + (threadIdx.x >> 5);
    if (e >= E) return;
    int lane = threadIdx.x & 31;

    int   s = __ldg(src + e);
    int   d = __ldg(dst + e);
    int   t = __ldg(et + e);
    float n = __ldg(enorm + e);

    int c = lane * 4;
    float4 a = *(const float4*)(hW   + (size_t)s * 128 + c);
    float4 b = *(const float4*)(relW + (size_t)t * 128 + c);
    float4 v = make_float4((a.x + b.x) * n, (a.y + b.y) * n,
                           (a.z + b.z) * n, (a.w + b.w) * n);
    float* p = agg + (size_t)d * 128 + c;
    asm volatile("red.global.add.v4.f32 [%0], {%1,%2,%3,%4};"
                 :: "l"(p), "f"(v.x), "f"(v.y), "f"(v.z), "f"(v.w)
                 : "memory");
}

// ---------------------------------------------------------------------------
// Kernel D: h_cur = rrelu(agg); gate = sigmoid(h_cur@Wt + b);
// out = gate*h_cur + (1-gate)*his.  In-place on d_out.
// ---------------------------------------------------------------------------
extern "C" __global__ void __launch_bounds__(512)
k_final(float* __restrict__ x,
        const float* __restrict__ Wt,
        const float* __restrict__ bias,
        const float* __restrict__ his,
        int N)
{
    extern __shared__ float sm[];
    float* Wsh = sm;             // 128*128
    float* hs  = sm + 128 * 128; // 64*128 (post-rrelu h_cur)
    const int tid  = threadIdx.x;
    const int base = blockIdx.x * 64;
    const int lane = tid & 31;
    const int w    = tid >> 5;

    for (int t = tid; t < (128 * 128) / 4; t += 512)
        *(float4*)(Wsh + t * 4) = *(const float4*)(Wt + t * 4);

    #pragma unroll
    for (int rr = 0; rr < 4; rr++) {
        int row  = w * 4 + rr;
        int node = base + row;
        float4 v = make_float4(0.f, 0.f, 0.f, 0.f);
        if (node < N) v = *(const float4*)(x + (size_t)node * 128 + lane * 4);
        v.x = v.x >= 0.f ? v.x : RRELU_SLOPE * v.x;
        v.y = v.y >= 0.f ? v.y : RRELU_SLOPE * v.y;
        v.z = v.z >= 0.f ? v.z : RRELU_SLOPE * v.z;
        v.w = v.w >= 0.f ? v.w : RRELU_SLOPE * v.w;
        *(float4*)(hs + row * 128 + lane * 4) = v;
    }
    __syncthreads();

    const int r0 = w * 4;
    ull acc[4][2];
    #pragma unroll
    for (int j = 0; j < 4; j++) acc[j][0] = acc[j][1] = pack2(0.f, 0.f);

    #pragma unroll 2
    for (int kk = 0; kk < 128; kk += 4) {
        float a[4][4];
        #pragma unroll
        for (int j = 0; j < 4; j++) {
            float4 v = *(const float4*)(hs + (r0 + j) * 128 + kk);
            a[j][0] = v.x; a[j][1] = v.y; a[j][2] = v.z; a[j][3] = v.w;
        }
        #pragma unroll
        for (int t = 0; t < 4; t++) {
            float4 b = *(const float4*)(Wsh + (kk + t) * 128 + lane * 4);
            ull b0 = pack2(b.x, b.y), b1 = pack2(b.z, b.w);
            #pragma unroll
            for (int j = 0; j < 4; j++) {
                ull ap = pack2(a[j][t], a[j][t]);
                ffma2(acc[j][0], ap, b0);
                ffma2(acc[j][1], ap, b1);
            }
        }
    }

    float4 bv = *(const float4*)(bias + lane * 4);

    #pragma unroll
    for (int j = 0; j < 4; j++) {
        int node = base + r0 + j;
        if (node >= N) continue;
        float g0, g1, g2, g3;
        unpack2(acc[j][0], g0, g1); unpack2(acc[j][1], g2, g3);
        float4 hv = *(const float4*)(hs + (r0 + j) * 128 + lane * 4);
        float4 hh = *(const float4*)(his + (size_t)node * 128 + lane * 4);
        float s0 = 1.0f / (1.0f + __expf(-(g0 + bv.x)));
        float s1 = 1.0f / (1.0f + __expf(-(g1 + bv.y)));
        float s2 = 1.0f / (1.0f + __expf(-(g2 + bv.z)));
        float s3 = 1.0f / (1.0f + __expf(-(g3 + bv.w)));
        float4 o = make_float4(s0 * hv.x + (1.f - s0) * hh.x,
                               s1 * hv.y + (1.f - s1) * hh.y,
                               s2 * hv.z + (1.f - s2) * hh.z,
                               s3 * hv.w + (1.f - s3) * hh.w);
        *(float4*)(x + (size_t)node * 128 + lane * 4) = o;
    }
}

// ---------------------------------------------------------------------------
extern "C" void kernel_launch(void* const* d_in, const int* in_sizes, int n_in,
                              void* d_out, int out_size)
{
    const float* ent   = (const float*)d_in[0];
    const float* rel   = (const float*)d_in[1];
    const float* his   = (const float*)d_in[2];
    const float* Wn    = (const float*)d_in[3];
    const float* Ws    = (const float*)d_in[4];
    const float* Wt    = (const float*)d_in[5];
    const float* bias  = (const float*)d_in[6];
    const float* enorm = (const float*)d_in[7];
    const int*   src   = (const int*)d_in[8];
    const int*   dst   = (const int*)d_in[9];
    const int*   et    = (const int*)d_in[10];

    int N = in_sizes[0] / DHID;
    int R = in_sizes[1] / DHID;
    int E = in_sizes[7];
    float* out = (float*)d_out;

    float *hW, *relW;
    cudaGetSymbolAddress((void**)&hW, g_hW);
    cudaGetSymbolAddress((void**)&relW, g_relW);

    const int smA = (128 * 256 + 64 * 128) * sizeof(float); // 160 KB
    const int smB = (128 * 128 + 64 * 128) * sizeof(float); //  96 KB
    cudaFuncSetAttribute(k_norm_dual_gemm, cudaFuncAttributeMaxDynamicSharedMemorySize, smA);
    cudaFuncSetAttribute(k_rel_gemm,       cudaFuncAttributeMaxDynamicSharedMemorySize, smB);
    cudaFuncSetAttribute(k_final,          cudaFuncAttributeMaxDynamicSharedMemorySize, smB);

    k_norm_dual_gemm<<<(N + 63) / 64, 512, smA>>>(ent, Wn, Ws, hW, out, N);
    k_rel_gemm<<<(R + 63) / 64, 512, smB>>>(rel, Wn, relW, R);
    k_edge<<<(E + 7) / 8, 256>>>(hW, relW, enorm, src, dst, et, out, E);
    k_final<<<(N + 63) / 64, 512, smB>>>(out, Wt, bias, his, N);
}